// round 2
// baseline (speedup 1.0000x reference)
#include <cuda_runtime.h>

#define NT 512

namespace {
constexpr int KSZ = 11;
constexpr int T = 64;                 // output tile
constexpr int RROWS = 84;             // T + 20 (two-stage halo)
constexpr int RSTRIDE = 85;
constexpr int MROWS = 74;             // T + 10 (mu / product grid)
constexpr int MSTRIDE = 75;
constexpr int BSTRIDE = 65;
constexpr int IMG = 1024;
constexpr long long NPIX = 16LL * 1024 * 1024;

// shared-memory layout (floats)
constexpr int OFF_S1  = 0;
constexpr int OFF_S2  = OFF_S1  + RROWS * RSTRIDE;   // 7140
constexpr int OFF_TH  = OFF_S2  + RROWS * RSTRIDE;   // 14280
constexpr int OFF_M1  = OFF_TH  + RROWS * MSTRIDE;   // 20580
constexpr int OFF_M2  = OFF_M1  + MROWS * MSTRIDE;
constexpr int OFF_P11 = OFF_M2  + MROWS * MSTRIDE;
constexpr int OFF_P22 = OFF_P11 + MROWS * MSTRIDE;
constexpr int OFF_P12 = OFF_P22 + MROWS * MSTRIDE;
constexpr int SMEM_FLOATS = OFF_P12 + MROWS * MSTRIDE;  // 48330 -> ~193.3 KB
}

__device__ int    g_min_bits;
__device__ int    g_max_bits;
__device__ double g_sum;
__device__ float  g_w[KSZ];

// ---------------------------------------------------------------------------
// K0: per-launch reset + derive separable 1D weights from the 2D kernel.
// k2d = outer(g, g), sum(g) = 1  =>  g[i] = sum_j k2d[i][j]
// ---------------------------------------------------------------------------
__global__ void k_init(const float* __restrict__ kern) {
    int t = threadIdx.x;
    if (t == 0) { g_min_bits = 0x7F800000; g_max_bits = 0; g_sum = 0.0; }
    if (t < KSZ) {
        float s = 0.f;
        #pragma unroll
        for (int j = 0; j < KSZ; j++) s += kern[t * KSZ + j];
        g_w[t] = s;
    }
}

// ---------------------------------------------------------------------------
// K1: global min/max of both images (values are >= 0, so int-bit compare works)
// ---------------------------------------------------------------------------
__global__ void k_minmax(const float4* __restrict__ a, const float4* __restrict__ b, int n4) {
    float mn = __int_as_float(0x7F800000);
    float mx = 0.f;
    int stride = gridDim.x * blockDim.x;
    for (int i = blockIdx.x * blockDim.x + threadIdx.x; i < n4; i += stride) {
        float4 x = a[i], y = b[i];
        mn = fminf(mn, fminf(fminf(x.x, x.y), fminf(x.z, x.w)));
        mx = fmaxf(mx, fmaxf(fmaxf(x.x, x.y), fmaxf(x.z, x.w)));
        mn = fminf(mn, fminf(fminf(y.x, y.y), fminf(y.z, y.w)));
        mx = fmaxf(mx, fmaxf(fmaxf(y.x, y.y), fmaxf(y.z, y.w)));
    }
    #pragma unroll
    for (int o = 16; o; o >>= 1) {
        mn = fminf(mn, __shfl_xor_sync(0xFFFFFFFFu, mn, o));
        mx = fmaxf(mx, __shfl_xor_sync(0xFFFFFFFFu, mx, o));
    }
    if ((threadIdx.x & 31) == 0) {
        atomicMin(&g_min_bits, __float_as_int(mn));
        atomicMax(&g_max_bits, __float_as_int(mx));
    }
}

// ---------------------------------------------------------------------------
// Separable blur helpers: each thread produces a strip of 4 outputs
// (14 loads + 44 FMA -> LDS/FMA ratio 0.32, FMA-pipe bound).
// Out-of-range halo reads stay inside total dynamic smem; results discarded.
// ---------------------------------------------------------------------------
template<int ROWS, int OUTC, int SRCS, int DSTS>
__device__ __forceinline__ void hblur4(const float* __restrict__ src, float* __restrict__ dst,
                                       const float* __restrict__ sw, int tid) {
    constexpr int G = (OUTC + 3) / 4;
    for (int i = tid; i < ROWS * G; i += NT) {
        int row = i / G;
        int c4 = (i - row * G) * 4;
        const float* s = src + row * SRCS + c4;
        float v[14];
        #pragma unroll
        for (int j = 0; j < 14; j++) v[j] = s[j];
        float a0 = 0.f, a1 = 0.f, a2 = 0.f, a3 = 0.f;
        #pragma unroll
        for (int k = 0; k < KSZ; k++) {
            float w = sw[k];
            a0 = fmaf(w, v[k],     a0);
            a1 = fmaf(w, v[k + 1], a1);
            a2 = fmaf(w, v[k + 2], a2);
            a3 = fmaf(w, v[k + 3], a3);
        }
        float* d = dst + row * DSTS + c4;
        d[0] = a0;
        if (c4 + 1 < OUTC) d[1] = a1;
        if (c4 + 2 < OUTC) d[2] = a2;
        if (c4 + 3 < OUTC) d[3] = a3;
    }
}

template<int OUTR, int COLS, int SRCS, int DSTS>
__device__ __forceinline__ void vblur4(const float* __restrict__ src, float* __restrict__ dst,
                                       const float* __restrict__ sw, int tid) {
    constexpr int G = (OUTR + 3) / 4;
    for (int i = tid; i < G * COLS; i += NT) {
        int rg = i / COLS;
        int c  = i - rg * COLS;
        int r4 = rg * 4;
        const float* s = src + r4 * SRCS + c;
        float v[14];
        #pragma unroll
        for (int j = 0; j < 14; j++) v[j] = s[j * SRCS];
        float a0 = 0.f, a1 = 0.f, a2 = 0.f, a3 = 0.f;
        #pragma unroll
        for (int k = 0; k < KSZ; k++) {
            float w = sw[k];
            a0 = fmaf(w, v[k],     a0);
            a1 = fmaf(w, v[k + 1], a1);
            a2 = fmaf(w, v[k + 2], a2);
            a3 = fmaf(w, v[k + 3], a3);
        }
        float* d = dst + r4 * DSTS + c;
        d[0] = a0;
        if (r4 + 1 < OUTR) d[DSTS]     = a1;
        if (r4 + 2 < OUTR) d[2 * DSTS] = a2;
        if (r4 + 3 < OUTR) d[3 * DSTS] = a3;
    }
}

// ---------------------------------------------------------------------------
// K2: fully fused tiled SSIM. One 64x64 output tile per block, halo 10.
// ---------------------------------------------------------------------------
__global__ __launch_bounds__(NT, 1)
void k_ssim(const float* __restrict__ img1, const float* __restrict__ img2) {
    extern __shared__ float sm[];
    __shared__ float sw[KSZ];
    __shared__ float red[NT / 32];

    int tid = threadIdx.x;
    if (tid < KSZ) sw[tid] = g_w[tid];

    float mn = __int_as_float(g_min_bits);
    float mx = __int_as_float(g_max_bits);
    float vr = mx - mn + 1e-5f;
    float C1 = 0.01f * vr; C1 *= C1;
    float C2 = 0.03f * vr; C2 *= C2;

    int bx = blockIdx.x, by = blockIdx.y, bz = blockIdx.z;
    const float* i1 = img1 + (size_t)bz * (IMG * IMG);
    const float* i2 = img2 + (size_t)bz * (IMG * IMG);
    int y0 = by * T - 10;
    int x0 = bx * T - 10;

    float* s1  = sm + OFF_S1;
    float* s2  = sm + OFF_S2;
    float* tH  = sm + OFF_TH;
    float* m1  = sm + OFF_M1;
    float* m2  = sm + OFF_M2;
    float* p11 = sm + OFF_P11;
    float* p22 = sm + OFF_P22;
    float* p12 = sm + OFF_P12;

    // Phase 1: load both tiles (zero outside the image -> matches 'same' zero pad)
    for (int i = tid; i < RROWS * RROWS; i += NT) {
        int r = i / RROWS, c = i - r * RROWS;
        int gy = y0 + r, gx = x0 + c;
        bool in = (gy >= 0 && gy < IMG && gx >= 0 && gx < IMG);
        int gi = gy * IMG + gx;
        s1[r * RSTRIDE + c] = in ? i1[gi] : 0.f;
        s2[r * RSTRIDE + c] = in ? i2[gi] : 0.f;
    }
    __syncthreads();

    // mu1, mu2 on the (T+10)^2 grid
    hblur4<RROWS, MROWS, RSTRIDE, MSTRIDE>(s1, tH, sw, tid);
    __syncthreads();
    vblur4<MROWS, MROWS, MSTRIDE, MSTRIDE>(tH, m1, sw, tid);
    __syncthreads();
    hblur4<RROWS, MROWS, RSTRIDE, MSTRIDE>(s2, tH, sw, tid);
    __syncthreads();
    vblur4<MROWS, MROWS, MSTRIDE, MSTRIDE>(tH, m2, sw, tid);
    __syncthreads();

    // d-products; MUST be zero outside the image (second conv pads the product
    // array with zeros — NOT the padded-mu value)
    int my0 = y0 + 5, mx0 = x0 + 5;
    for (int i = tid; i < MROWS * MROWS; i += NT) {
        int r = i / MROWS, c = i - r * MROWS;
        int gy = my0 + r, gx = mx0 + c;
        bool in = (gy >= 0 && gy < IMG && gx >= 0 && gx < IMG);
        float d1 = s1[(r + 5) * RSTRIDE + (c + 5)] - m1[r * MSTRIDE + c];
        float d2 = s2[(r + 5) * RSTRIDE + (c + 5)] - m2[r * MSTRIDE + c];
        p11[r * MSTRIDE + c] = in ? d1 * d1 : 0.f;
        p22[r * MSTRIDE + c] = in ? d2 * d2 : 0.f;
        p12[r * MSTRIDE + c] = in ? d1 * d2 : 0.f;
    }
    __syncthreads();

    // blur the three products; results overwrite now-dead buffers
    float* b11 = s1;
    float* b22 = s2;
    float* b12 = p11;

    hblur4<MROWS, T, MSTRIDE, MSTRIDE>(p11, tH, sw, tid);
    __syncthreads();
    vblur4<T, T, MSTRIDE, BSTRIDE>(tH, b11, sw, tid);
    __syncthreads();
    hblur4<MROWS, T, MSTRIDE, MSTRIDE>(p22, tH, sw, tid);
    __syncthreads();
    vblur4<T, T, MSTRIDE, BSTRIDE>(tH, b22, sw, tid);
    __syncthreads();
    hblur4<MROWS, T, MSTRIDE, MSTRIDE>(p12, tH, sw, tid);
    __syncthreads();
    vblur4<T, T, MSTRIDE, BSTRIDE>(tH, b12, sw, tid);
    __syncthreads();

    // combine + reduce (single division per pixel)
    float acc = 0.f;
    for (int i = tid; i < T * T; i += NT) {
        int r = i >> 6, c = i & 63;
        float s11 = b11[r * BSTRIDE + c] + 1.f;
        float s22 = b22[r * BSTRIDE + c] + 1.f;
        float s12 = b12[r * BSTRIDE + c] + 1.f;
        float u1 = m1[(r + 5) * MSTRIDE + (c + 5)];
        float u2 = m2[(r + 5) * MSTRIDE + (c + 5)];
        float m11 = u1 * u1 + 1.f;
        float m22 = u2 * u2 + 1.f;
        float m12 = u1 * u2 + 1.f;
        float t2 = 2.f * m12;
        float t1 = m11 + m22;
        float num = (2.f * s12 + C2) * (t2 * t2 + C1);
        float den = (s11 + s22 + C2) * (t1 * t1 + C1);
        acc += __fdividef(num, den);
    }
    #pragma unroll
    for (int o = 16; o; o >>= 1) acc += __shfl_xor_sync(0xFFFFFFFFu, acc, o);
    if ((tid & 31) == 0) red[tid >> 5] = acc;
    __syncthreads();
    if (tid < 32) {
        float v = (tid < NT / 32) ? red[tid] : 0.f;
        #pragma unroll
        for (int o = 8; o; o >>= 1) v += __shfl_xor_sync(0xFFFFFFFFu, v, o);
        if (tid == 0) atomicAdd(&g_sum, (double)v);
    }
}

// ---------------------------------------------------------------------------
// K3: finalize scalar output
// ---------------------------------------------------------------------------
__global__ void k_final(float* __restrict__ out) {
    out[0] = 1.0f - (float)(g_sum * (1.0 / (double)NPIX));
}

// ---------------------------------------------------------------------------
extern "C" void kernel_launch(void* const* d_in, const int* in_sizes, int n_in,
                              void* d_out, int out_size) {
    const float* img1 = (const float*)d_in[0];
    const float* img2 = (const float*)d_in[1];
    const float* kern = (const float*)d_in[2];
    float* out = (float*)d_out;

    cudaFuncSetAttribute(k_ssim, cudaFuncAttributeMaxDynamicSharedMemorySize,
                         SMEM_FLOATS * (int)sizeof(float));

    k_init<<<1, 32>>>(kern);
    k_minmax<<<1024, 256>>>((const float4*)img1, (const float4*)img2,
                            (int)(NPIX / 4));
    dim3 grid(IMG / T, IMG / T, 16);
    k_ssim<<<grid, NT, SMEM_FLOATS * (int)sizeof(float)>>>(img1, img2);
    k_final<<<1, 1>>>(out);
}

// round 3
// speedup vs baseline: 1.1825x; 1.1825x over previous
#include <cuda_runtime.h>

#define NT 512

namespace {
constexpr int KSZ = 11;
constexpr int T = 64;
constexpr int IMG = 1024;
constexpr long long NPIX = 16LL * 1024 * 1024;

constexpr int RROWS = 84;     // T + 20
constexpr int RST   = 88;     // padded stride (mult of 4)
constexpr int MROWS = 74;     // T + 10
constexpr int MST   = 76;     // mult of 4
constexpr int QST   = 64;

// shared layout (floats), all offsets mult of 4
constexpr int OFF_S1  = 0;
constexpr int OFF_S2  = OFF_S1 + RROWS * RST;        // 7392
constexpr int OFF_TH1 = OFF_S2 + RROWS * RST;        // 14784
constexpr int OFF_TH2 = OFF_TH1 + RROWS * MST;       // 21168
constexpr int OFF_TH3 = OFF_TH2 + RROWS * MST;       // 27552
constexpr int OFF_M1  = OFF_TH3 + RROWS * MST;       // 33936
constexpr int OFF_M2  = OFF_M1 + MROWS * MST;        // 39560
constexpr int SMEM_FLOATS = OFF_M2 + MROWS * MST;    // 45184 -> 180.7 KB
// blurred products reuse the s1/s2 region (dead by then)
constexpr int OFF_Q1 = 0;
constexpr int OFF_Q2 = MROWS * QST;                  // 4736
constexpr int OFF_Q3 = 2 * MROWS * QST;              // 9472
}

__device__ int    g_min_bits;
__device__ int    g_max_bits;
__device__ double g_sum;
__device__ float  g_w[KSZ];

typedef unsigned long long ull;

__device__ __forceinline__ void ffma2(ull& d, ull a, ull b) {
    asm("fma.rn.f32x2 %0, %1, %2, %3;" : "=l"(d) : "l"(a), "l"(b), "l"(d));
}
union F2U { float2 f; ull u; };

// ---------------------------------------------------------------------------
__global__ void k_init(const float* __restrict__ kern) {
    int t = threadIdx.x;
    if (t == 0) { g_min_bits = 0x7F800000; g_max_bits = 0; g_sum = 0.0; }
    if (t < KSZ) {
        float s = 0.f;
        #pragma unroll
        for (int j = 0; j < KSZ; j++) s += kern[t * KSZ + j];
        g_w[t] = s;
    }
}

// ---------------------------------------------------------------------------
__global__ void k_minmax(const float4* __restrict__ a, const float4* __restrict__ b, int n4) {
    float mn = __int_as_float(0x7F800000);
    float mx = 0.f;
    int stride = gridDim.x * blockDim.x;
    for (int i = blockIdx.x * blockDim.x + threadIdx.x; i < n4; i += stride) {
        float4 x = a[i], y = b[i];
        mn = fminf(mn, fminf(fminf(x.x, x.y), fminf(x.z, x.w)));
        mx = fmaxf(mx, fmaxf(fmaxf(x.x, x.y), fmaxf(x.z, x.w)));
        mn = fminf(mn, fminf(fminf(y.x, y.y), fminf(y.z, y.w)));
        mx = fmaxf(mx, fmaxf(fmaxf(y.x, y.y), fmaxf(y.z, y.w)));
    }
    #pragma unroll
    for (int o = 16; o; o >>= 1) {
        mn = fminf(mn, __shfl_xor_sync(0xFFFFFFFFu, mn, o));
        mx = fmaxf(mx, __shfl_xor_sync(0xFFFFFFFFu, mx, o));
    }
    if ((threadIdx.x & 31) == 0) {
        atomicMin(&g_min_bits, __float_as_int(mn));
        atomicMax(&g_max_bits, __float_as_int(mx));
    }
}

// ---------------------------------------------------------------------------
__global__ __launch_bounds__(NT, 1)
void k_ssim(const float* __restrict__ img1, const float* __restrict__ img2) {
    extern __shared__ float sm[];
    __shared__ float sw[KSZ];
    __shared__ ull   sw2[KSZ];
    __shared__ float red[NT / 32];

    const int tid = threadIdx.x;
    if (tid < KSZ) {
        float w = g_w[tid];
        sw[tid] = w;
        F2U u; u.f = make_float2(w, w);
        sw2[tid] = u.u;
    }

    const float mnv = __int_as_float(g_min_bits);
    const float mxv = __int_as_float(g_max_bits);
    const float vr = mxv - mnv + 1e-5f;
    float C1 = 0.01f * vr; C1 *= C1;
    float C2 = 0.03f * vr; C2 *= C2;

    const int bx = blockIdx.x, by = blockIdx.y, bz = blockIdx.z;
    const float* i1 = img1 + (size_t)bz * (IMG * IMG);
    const float* i2 = img2 + (size_t)bz * (IMG * IMG);
    const int y0 = by * T - 10;
    const int x0 = bx * T - 10;

    float* s1  = sm + OFF_S1;
    float* s2  = sm + OFF_S2;
    float* tH1 = sm + OFF_TH1;
    float* tH2 = sm + OFF_TH2;
    float* tH3 = sm + OFF_TH3;
    float* m1  = sm + OFF_M1;
    float* m2  = sm + OFF_M2;

    // ---- P0: load (covers the full padded stride; OOB -> 0) -------------
    for (int i = tid; i < RROWS * RST; i += NT) {
        int r = i / RST, c = i - r * RST;
        int gy = y0 + r, gx = x0 + c;
        bool in = (gy >= 0 && gy < IMG && gx >= 0 && gx < IMG);
        int gi = gy * IMG + gx;
        s1[i] = in ? i1[gi] : 0.f;
        s2[i] = in ? i2[gi] : 0.f;
    }
    __syncthreads();

    // ---- P1: horizontal blur of both images (84 rows x 19 col-groups x 2)
    for (int it = tid; it < 2 * RROWS * 19; it += NT) {
        int img = it >= RROWS * 19;
        int t2 = it - img * RROWS * 19;
        int row = t2 / 19, c4 = (t2 - row * 19) * 4;
        const float* src = (img ? s2 : s1) + row * RST + c4;
        float vf[16];
        #pragma unroll
        for (int q = 0; q < 4; q++) {
            float4 v = *(const float4*)(src + 4 * q);
            vf[4 * q] = v.x; vf[4 * q + 1] = v.y; vf[4 * q + 2] = v.z; vf[4 * q + 3] = v.w;
        }
        float a0 = 0.f, a1 = 0.f, a2 = 0.f, a3 = 0.f;
        #pragma unroll
        for (int k = 0; k < KSZ; k++) {
            float w = sw[k];
            a0 = fmaf(w, vf[k], a0);
            a1 = fmaf(w, vf[k + 1], a1);
            a2 = fmaf(w, vf[k + 2], a2);
            a3 = fmaf(w, vf[k + 3], a3);
        }
        *(float4*)((img ? tH2 : tH1) + row * MST + c4) = make_float4(a0, a1, a2, a3);
    }
    __syncthreads();

    // ---- P2: vertical blur -> m1, m2 (f32x2; 2-row x 4-col blocks) ------
    // items: 2 imgs * 37 row-pairs * 19 col-groups = 1406
    for (int it = tid; it < 2 * 37 * 19; it += NT) {
        int img = it >= 37 * 19;
        int t2 = it - img * 37 * 19;
        int rg = t2 / 19, c4 = (t2 - rg * 19) * 4;
        int r2 = rg * 2;
        const float* src = (img ? tH2 : tH1) + r2 * MST + c4;
        ull v[12][2];
        #pragma unroll
        for (int j = 0; j < 12; j++) {
            ulonglong2 q = *(const ulonglong2*)(src + j * MST);
            v[j][0] = q.x; v[j][1] = q.y;
        }
        ull a00 = 0, a01 = 0, a10 = 0, a11 = 0;
        #pragma unroll
        for (int k = 0; k < KSZ; k++) {
            ull wk = sw2[k];
            ffma2(a00, wk, v[k][0]);     ffma2(a01, wk, v[k][1]);
            ffma2(a10, wk, v[k + 1][0]); ffma2(a11, wk, v[k + 1][1]);
        }
        float* dst = (img ? m2 : m1) + r2 * MST + c4;
        *(ulonglong2*)dst = make_ulonglong2(a00, a01);
        *(ulonglong2*)(dst + MST) = make_ulonglong2(a10, a11);
    }
    __syncthreads();

    // ---- P3: products (zeroed outside the image) -> tH1/tH2/tH3 ---------
    {
        int my0 = y0 + 5, mx0 = x0 + 5;
        for (int i = tid; i < MROWS * MST; i += NT) {
            int r = i / MST, c = i - r * MST;
            int gy = my0 + r, gx = mx0 + c;
            bool in = (gy >= 0 && gy < IMG && gx >= 0 && gx < IMG);
            float d1 = s1[(r + 5) * RST + (c + 5)] - m1[i];
            float d2 = s2[(r + 5) * RST + (c + 5)] - m2[i];
            tH1[i] = in ? d1 * d1 : 0.f;
            tH2[i] = in ? d2 * d2 : 0.f;
            tH3[i] = in ? d1 * d2 : 0.f;
        }
    }
    __syncthreads();

    // ---- P4: horizontal blur of 3 products -> q (stride 64, in s-region)
    // items: 3 products * 74 rows * 16 col-groups = 3552
    for (int it = tid; it < 3 * MROWS * 16; it += NT) {
        int p = it / (MROWS * 16);
        int t2 = it - p * (MROWS * 16);
        int row = t2 / 16, c4 = (t2 - row * 16) * 4;
        const float* src = (p == 0 ? tH1 : (p == 1 ? tH2 : tH3)) + row * MST + c4;
        float vf[16];
        #pragma unroll
        for (int q = 0; q < 4; q++) {
            float4 v = *(const float4*)(src + 4 * q);
            vf[4 * q] = v.x; vf[4 * q + 1] = v.y; vf[4 * q + 2] = v.z; vf[4 * q + 3] = v.w;
        }
        float a0 = 0.f, a1 = 0.f, a2 = 0.f, a3 = 0.f;
        #pragma unroll
        for (int k = 0; k < KSZ; k++) {
            float w = sw[k];
            a0 = fmaf(w, vf[k], a0);
            a1 = fmaf(w, vf[k + 1], a1);
            a2 = fmaf(w, vf[k + 2], a2);
            a3 = fmaf(w, vf[k + 3], a3);
        }
        float* dst = sm + (p == 0 ? OFF_Q1 : (p == 1 ? OFF_Q2 : OFF_Q3));
        *(float4*)(dst + row * QST + c4) = make_float4(a0, a1, a2, a3);
    }
    __syncthreads();

    // ---- P5: vertical blur of 3 products + combine (fused, no stores) ---
    // items: 32 row-pairs * 16 col-groups = 512 (exactly NT)
    float acc = 0.f;
    {
        int it = tid;  // one item per thread
        int rg = it / 16, c4 = (it - rg * 16) * 4;
        int r2 = rg * 2;
        float s11[8], s22[8], s12[8];  // 2 rows x 4 cols each
        #pragma unroll
        for (int p = 0; p < 3; p++) {
            const float* src = sm + (p == 0 ? OFF_Q1 : (p == 1 ? OFF_Q2 : OFF_Q3))
                               + r2 * QST + c4;
            ull v[12][2];
            #pragma unroll
            for (int j = 0; j < 12; j++) {
                ulonglong2 q = *(const ulonglong2*)(src + j * QST);
                v[j][0] = q.x; v[j][1] = q.y;
            }
            ull a00 = 0, a01 = 0, a10 = 0, a11 = 0;
            #pragma unroll
            for (int k = 0; k < KSZ; k++) {
                ull wk = sw2[k];
                ffma2(a00, wk, v[k][0]);     ffma2(a01, wk, v[k][1]);
                ffma2(a10, wk, v[k + 1][0]); ffma2(a11, wk, v[k + 1][1]);
            }
            float* dst = (p == 0 ? s11 : (p == 1 ? s22 : s12));
            F2U u;
            u.u = a00; dst[0] = u.f.x; dst[1] = u.f.y;
            u.u = a01; dst[2] = u.f.x; dst[3] = u.f.y;
            u.u = a10; dst[4] = u.f.x; dst[5] = u.f.y;
            u.u = a11; dst[6] = u.f.x; dst[7] = u.f.y;
        }
        #pragma unroll
        for (int i = 0; i < 2; i++) {
            #pragma unroll
            for (int j = 0; j < 4; j++) {
                int idx = i * 4 + j;
                float u1 = m1[(r2 + 5 + i) * MST + (c4 + 5 + j)];
                float u2 = m2[(r2 + 5 + i) * MST + (c4 + 5 + j)];
                float a = s11[idx] + 1.f;
                float b = s22[idx] + 1.f;
                float c = s12[idx] + 1.f;
                float m11 = u1 * u1 + 1.f;
                float m22 = u2 * u2 + 1.f;
                float m12 = u1 * u2 + 1.f;
                float t2v = 2.f * m12;
                float t1v = m11 + m22;
                float num = (2.f * c + C2) * (t2v * t2v + C1);
                float den = (a + b + C2) * (t1v * t1v + C1);
                acc += __fdividef(num, den);
            }
        }
    }
    #pragma unroll
    for (int o = 16; o; o >>= 1) acc += __shfl_xor_sync(0xFFFFFFFFu, acc, o);
    if ((tid & 31) == 0) red[tid >> 5] = acc;
    __syncthreads();
    if (tid < 32) {
        float v = (tid < NT / 32) ? red[tid] : 0.f;
        #pragma unroll
        for (int o = 8; o; o >>= 1) v += __shfl_xor_sync(0xFFFFFFFFu, v, o);
        if (tid == 0) atomicAdd(&g_sum, (double)v);
    }
}

// ---------------------------------------------------------------------------
__global__ void k_final(float* __restrict__ out) {
    out[0] = 1.0f - (float)(g_sum * (1.0 / (double)NPIX));
}

// ---------------------------------------------------------------------------
extern "C" void kernel_launch(void* const* d_in, const int* in_sizes, int n_in,
                              void* d_out, int out_size) {
    const float* img1 = (const float*)d_in[0];
    const float* img2 = (const float*)d_in[1];
    const float* kern = (const float*)d_in[2];
    float* out = (float*)d_out;

    cudaFuncSetAttribute(k_ssim, cudaFuncAttributeMaxDynamicSharedMemorySize,
                         SMEM_FLOATS * (int)sizeof(float));

    k_init<<<1, 32>>>(kern);
    k_minmax<<<1024, 256>>>((const float4*)img1, (const float4*)img2,
                            (int)(NPIX / 4));
    dim3 grid(IMG / T, IMG / T, 16);
    k_ssim<<<grid, NT, SMEM_FLOATS * (int)sizeof(float)>>>(img1, img2);
    k_final<<<1, 1>>>(out);
}